// round 1
// baseline (speedup 1.0000x reference)
#include <cuda_runtime.h>
#include <math.h>

#define D_ 128
#define K_ 8

// Sum-reduce across the 16 lanes of a half-warp (all lanes end with the total).
__device__ __forceinline__ float hred16(float v) {
    v += __shfl_xor_sync(0xffffffffu, v, 8, 16);
    v += __shfl_xor_sync(0xffffffffu, v, 4, 16);
    v += __shfl_xor_sync(0xffffffffu, v, 2, 16);
    v += __shfl_xor_sync(0xffffffffu, v, 1, 16);
    return v;
}

__global__ __launch_bounds__(256, 2) void l1q_kernel(
    const float* __restrict__ X,      // (B, 128)
    const float* __restrict__ W,      // (128, 128)
    const float* __restrict__ bias,   // (128,)
    const float* __restrict__ gamma,  // (128,)
    const float* __restrict__ beta,   // (128,)
    const float* __restrict__ cb,     // (8, 128)
    float* __restrict__ out,
    int B, long out_size)
{
    __shared__ float As[16][128];        // x tile, [k][row]
    __shared__ float Bs[16][128];        // W tile, [k][outcol]  (h[r][j] = sum_i x[r][i]*W[j][i])
    __shared__ float s_cb[K_][D_];       // raw codebook (for embedding gather)
    __shared__ float s_cbn[K_][D_];      // l2-normalized codebook
    __shared__ float s_g[D_], s_b[D_], s_bias[D_];

    const int tid = threadIdx.x;

    // ---- one-time block init ----
    for (int i = tid; i < K_ * D_; i += 256) ((float*)s_cb)[i] = cb[i];
    if (tid < D_) { s_g[tid] = gamma[tid]; s_b[tid] = beta[tid]; s_bias[tid] = bias[tid]; }
    __syncthreads();
    if (tid < K_) {
        float s = 0.f;
        #pragma unroll 8
        for (int j = 0; j < D_; ++j) { float v = s_cb[tid][j]; s += v * v; }
        float inv = 1.f / fmaxf(sqrtf(s), 1e-12f);
        for (int j = 0; j < D_; ++j) s_cbn[tid][j] = s_cb[tid][j] * inv;
    }
    // (s_cbn consumed only after the GEMM loop's syncthreads)

    // ---- main GEMM: 128 rows x 128 cols per block, 8x8 per thread ----
    const int tx = tid & 15;            // output-column group
    const int ty = tid >> 4;            // row group
    const int row0 = blockIdx.x * 128;
    const int ldr = tid >> 2;           // 0..63
    const int ldc = (tid & 3) << 2;     // 0,4,8,12

    float acc[8][8];
    #pragma unroll
    for (int m = 0; m < 8; ++m)
        #pragma unroll
        for (int n = 0; n < 8; ++n) acc[m][n] = 0.f;

    int rA0 = row0 + ldr;      if (rA0 >= B) rA0 = B - 1;
    int rA1 = row0 + ldr + 64; if (rA1 >= B) rA1 = B - 1;

    #pragma unroll 1
    for (int t = 0; t < D_ / 16; ++t) {
        const int k0 = t * 16;
        float4 a0 = *(const float4*)(X + (long)rA0 * D_ + k0 + ldc);
        float4 a1 = *(const float4*)(X + (long)rA1 * D_ + k0 + ldc);
        float4 w0 = *(const float4*)(W + (long)ldr * D_ + k0 + ldc);
        float4 w1 = *(const float4*)(W + (long)(ldr + 64) * D_ + k0 + ldc);
        __syncthreads();
        As[ldc + 0][ldr] = a0.x; As[ldc + 1][ldr] = a0.y;
        As[ldc + 2][ldr] = a0.z; As[ldc + 3][ldr] = a0.w;
        As[ldc + 0][ldr + 64] = a1.x; As[ldc + 1][ldr + 64] = a1.y;
        As[ldc + 2][ldr + 64] = a1.z; As[ldc + 3][ldr + 64] = a1.w;
        Bs[ldc + 0][ldr] = w0.x; Bs[ldc + 1][ldr] = w0.y;
        Bs[ldc + 2][ldr] = w0.z; Bs[ldc + 3][ldr] = w0.w;
        Bs[ldc + 0][ldr + 64] = w1.x; Bs[ldc + 1][ldr + 64] = w1.y;
        Bs[ldc + 2][ldr + 64] = w1.z; Bs[ldc + 3][ldr + 64] = w1.w;
        __syncthreads();
        #pragma unroll
        for (int kk = 0; kk < 16; ++kk) {
            float ar[8], br[8];
            *(float4*)&ar[0] = *(const float4*)&As[kk][ty * 8];
            *(float4*)&ar[4] = *(const float4*)&As[kk][ty * 8 + 4];
            *(float4*)&br[0] = *(const float4*)&Bs[kk][tx * 8];
            *(float4*)&br[4] = *(const float4*)&Bs[kk][tx * 8 + 4];
            #pragma unroll
            for (int m = 0; m < 8; ++m)
                #pragma unroll
                for (int n = 0; n < 8; ++n)
                    acc[m][n] = fmaf(ar[m], br[n], acc[m][n]);
        }
    }
    __syncthreads();

    // ---- fused epilogue: LN -> l2norm -> logits -> softmax/argmax -> outputs ----
    const long Bl = (long)B;
    const long off_soft = Bl;
    const long off_emb  = Bl + Bl * K_;
    const long off_log  = Bl + Bl * K_ + Bl * D_;
    const int c0 = tx * 8;

    #pragma unroll 1
    for (int m = 0; m < 8; ++m) {
        const int r = row0 + ty * 8 + m;

        float hv[8];
        #pragma unroll
        for (int n = 0; n < 8; ++n) hv[n] = acc[m][n] + s_bias[c0 + n];

        float s = 0.f;
        #pragma unroll
        for (int n = 0; n < 8; ++n) s += hv[n];
        const float mu = hred16(s) * (1.f / 128.f);

        float q = 0.f;
        #pragma unroll
        for (int n = 0; n < 8; ++n) { float d = hv[n] - mu; q += d * d; }
        const float var = hred16(q) * (1.f / 128.f);
        const float rstd = rsqrtf(var + 1e-5f);

        float tv[8]; float nn = 0.f;
        #pragma unroll
        for (int n = 0; n < 8; ++n) {
            tv[n] = (hv[n] - mu) * rstd * s_g[c0 + n] + s_b[c0 + n];
            nn += tv[n] * tv[n];
        }
        nn = hred16(nn);
        const float inv = 1.f / fmaxf(sqrtf(nn), 1e-12f);

        float lg[8];
        #pragma unroll
        for (int k = 0; k < K_; ++k) {
            float p = 0.f;
            #pragma unroll
            for (int n = 0; n < 8; ++n) p = fmaf(tv[n], s_cbn[k][c0 + n], p);
            lg[k] = hred16(p) * inv;   // TEMPERATURE = 1.0
        }

        // argmax (first occurrence) + softmax, computed by every lane
        float mx = lg[0]; int idx = 0;
        #pragma unroll
        for (int k = 1; k < K_; ++k) if (lg[k] > mx) { mx = lg[k]; idx = k; }
        float e[8]; float se = 0.f;
        #pragma unroll
        for (int k = 0; k < K_; ++k) { e[k] = expf(lg[k] - mx); se += e[k]; }
        const float rse = 1.f / se;

        if (r < B) {
            // embedding = raw codebook[idx]  (straight-through == hard one-hot)
            long eb = off_emb + (long)r * D_ + c0;
            if (eb + 7 < out_size) {
                float4 v0 = *(const float4*)&s_cb[idx][c0];
                float4 v1 = *(const float4*)&s_cb[idx][c0 + 4];
                *(float4*)(out + eb)     = v0;
                *(float4*)(out + eb + 4) = v1;
            }
            if (tx == 0) {
                if (r < out_size) out[r] = (float)idx;
                long sb = off_soft + (long)r * K_;
                if (sb + 7 < out_size) {
                    #pragma unroll
                    for (int k = 0; k < K_; ++k) out[sb + k] = e[k] * rse;
                }
                long lb = off_log + (long)r * K_;
                if (lb + 7 < out_size) {
                    #pragma unroll
                    for (int k = 0; k < K_; ++k) out[lb + k] = lg[k];
                }
            }
        }
    }
}

extern "C" void kernel_launch(void* const* d_in, const int* in_sizes, int n_in,
                              void* d_out, int out_size) {
    const float* X     = (const float*)d_in[0];   // global_prosody (B,128)
    const float* W     = (const float*)d_in[1];   // (128,128)
    const float* bias  = (const float*)d_in[2];   // (128,)
    const float* gamma = (const float*)d_in[3];   // (128,)
    const float* beta  = (const float*)d_in[4];   // (128,)
    const float* cb    = (const float*)d_in[5];   // (8,128)
    float* out = (float*)d_out;

    const int B = in_sizes[0] / D_;
    const int grid = (B + 127) / 128;
    l1q_kernel<<<grid, 256>>>(X, W, bias, gamma, beta, cb, out, B, (long)out_size);
}

// round 2
// speedup vs baseline: 1.0077x; 1.0077x over previous
#include <cuda_runtime.h>
#include <math.h>

#define D_ 128
#define K_ 8

typedef unsigned long long u64;

// Sum-reduce across the 16 lanes of a half-warp (all lanes end with the total).
__device__ __forceinline__ float hred16(float v) {
    v += __shfl_xor_sync(0xffffffffu, v, 8, 16);
    v += __shfl_xor_sync(0xffffffffu, v, 4, 16);
    v += __shfl_xor_sync(0xffffffffu, v, 2, 16);
    v += __shfl_xor_sync(0xffffffffu, v, 1, 16);
    return v;
}

__global__ __launch_bounds__(256, 2) void l1q_kernel(
    const float* __restrict__ X,      // (B, 128)
    const float* __restrict__ W,      // (128, 128)
    const float* __restrict__ bias,   // (128,)
    const float* __restrict__ gamma,  // (128,)
    const float* __restrict__ beta,   // (128,)
    const float* __restrict__ cb,     // (8, 128)
    float* __restrict__ out,
    int B, long out_size)
{
    __shared__ float As[2][16][128];     // x tile, [buf][k][row]
    __shared__ float Bs[2][16][128];     // W tile, [buf][k][outcol]
    __shared__ float s_cb[K_][D_];       // raw codebook (embedding gather)
    __shared__ float s_cbn[K_][D_];      // l2-normalized codebook
    __shared__ float s_g[D_], s_b[D_], s_bias[D_];

    const int tid = threadIdx.x;

    // ---- one-time block init ----
    for (int i = tid; i < K_ * D_; i += 256) ((float*)s_cb)[i] = cb[i];
    if (tid < D_) { s_g[tid] = gamma[tid]; s_b[tid] = beta[tid]; s_bias[tid] = bias[tid]; }
    __syncthreads();
    if (tid < K_) {
        float s = 0.f;
        #pragma unroll 8
        for (int j = 0; j < D_; ++j) { float v = s_cb[tid][j]; s += v * v; }
        float inv = 1.f / fmaxf(sqrtf(s), 1e-12f);
        for (int j = 0; j < D_; ++j) s_cbn[tid][j] = s_cb[tid][j] * inv;
    }
    // (s_cbn consumed only after the GEMM loop's syncthreads)

    // ---- main GEMM: 128 rows x 128 cols per block, 8x8 per thread (FFMA2) ----
    const int tx = tid & 15;            // output-column group
    const int ty = tid >> 4;            // row group
    const int row0 = blockIdx.x * 128;
    const int ldr = tid & 63;           // 0..63  (warp-contiguous -> conflict-free STS)
    const int ldc = (tid >> 6) << 2;    // 0,4,8,12

    // packed accumulators: acc[m][j] = (c[m][2j], c[m][2j+1])
    u64 acc[8][4];
    #pragma unroll
    for (int m = 0; m < 8; ++m)
        #pragma unroll
        for (int j = 0; j < 4; ++j) acc[m][j] = 0ull;

    int rA0 = row0 + ldr;      if (rA0 >= B) rA0 = B - 1;
    int rA1 = row0 + ldr + 64; if (rA1 >= B) rA1 = B - 1;

    const float* pX0 = X + (long)rA0 * D_ + ldc;
    const float* pX1 = X + (long)rA1 * D_ + ldc;
    const float* pW0 = W + (long)ldr * D_ + ldc;
    const float* pW1 = W + (long)(ldr + 64) * D_ + ldc;

    // preload tile 0
    float4 a0 = *(const float4*)(pX0);
    float4 a1 = *(const float4*)(pX1);
    float4 w0 = *(const float4*)(pW0);
    float4 w1 = *(const float4*)(pW1);

    int buf = 0;
    #pragma unroll 1
    for (int t = 0; t < 8; ++t) {
        // stage current registers into smem (conflict-free STS.32)
        As[buf][ldc + 0][ldr] = a0.x; As[buf][ldc + 1][ldr] = a0.y;
        As[buf][ldc + 2][ldr] = a0.z; As[buf][ldc + 3][ldr] = a0.w;
        As[buf][ldc + 0][ldr + 64] = a1.x; As[buf][ldc + 1][ldr + 64] = a1.y;
        As[buf][ldc + 2][ldr + 64] = a1.z; As[buf][ldc + 3][ldr + 64] = a1.w;
        Bs[buf][ldc + 0][ldr] = w0.x; Bs[buf][ldc + 1][ldr] = w0.y;
        Bs[buf][ldc + 2][ldr] = w0.z; Bs[buf][ldc + 3][ldr] = w0.w;
        Bs[buf][ldc + 0][ldr + 64] = w1.x; Bs[buf][ldc + 1][ldr + 64] = w1.y;
        Bs[buf][ldc + 2][ldr + 64] = w1.z; Bs[buf][ldc + 3][ldr + 64] = w1.w;
        __syncthreads();

        // prefetch next tile (overlaps the FMA block below)
        if (t < 7) {
            const int k1 = (t + 1) * 16;
            a0 = *(const float4*)(pX0 + k1);
            a1 = *(const float4*)(pX1 + k1);
            w0 = *(const float4*)(pW0 + k1);
            w1 = *(const float4*)(pW1 + k1);
        }

        #pragma unroll
        for (int kk = 0; kk < 16; ++kk) {
            float4 af0 = *(const float4*)&As[buf][kk][ty * 8];
            float4 af1 = *(const float4*)&As[buf][kk][ty * 8 + 4];
            float4 bf0 = *(const float4*)&Bs[buf][kk][tx * 8];
            float4 bf1 = *(const float4*)&Bs[buf][kk][tx * 8 + 4];
            u64 b2[4];
            memcpy(&b2[0], &bf0.x, 8); memcpy(&b2[1], &bf0.z, 8);
            memcpy(&b2[2], &bf1.x, 8); memcpy(&b2[3], &bf1.z, 8);
            float ar[8] = {af0.x, af0.y, af0.z, af0.w, af1.x, af1.y, af1.z, af1.w};
            #pragma unroll
            for (int m = 0; m < 8; ++m) {
                u64 a2;
                asm("mov.b64 %0, {%1, %1};" : "=l"(a2) : "f"(ar[m]));
                #pragma unroll
                for (int j = 0; j < 4; ++j)
                    asm("fma.rn.f32x2 %0, %1, %2, %0;"
                        : "+l"(acc[m][j]) : "l"(a2), "l"(b2[j]));
            }
        }
        buf ^= 1;
    }
    __syncthreads();

    // ---- fused epilogue: LN -> l2norm -> logits -> softmax/argmax -> outputs ----
    const long Bl = (long)B;
    const long off_soft = Bl;
    const long off_emb  = Bl + Bl * K_;
    const long off_log  = Bl + Bl * K_ + Bl * D_;
    const int c0 = tx * 8;

    #pragma unroll 1
    for (int m = 0; m < 8; ++m) {
        const int r = row0 + ty * 8 + m;

        float hv[8];
        #pragma unroll
        for (int j = 0; j < 4; ++j)
            asm("mov.b64 {%0, %1}, %2;"
                : "=f"(hv[2 * j]), "=f"(hv[2 * j + 1]) : "l"(acc[m][j]));
        #pragma unroll
        for (int n = 0; n < 8; ++n) hv[n] += s_bias[c0 + n];

        float s = 0.f;
        #pragma unroll
        for (int n = 0; n < 8; ++n) s += hv[n];
        const float mu = hred16(s) * (1.f / 128.f);

        float q = 0.f;
        #pragma unroll
        for (int n = 0; n < 8; ++n) { float d = hv[n] - mu; q += d * d; }
        const float var = hred16(q) * (1.f / 128.f);
        const float rstd = rsqrtf(var + 1e-5f);

        float tv[8]; float nn = 0.f;
        #pragma unroll
        for (int n = 0; n < 8; ++n) {
            tv[n] = (hv[n] - mu) * rstd * s_g[c0 + n] + s_b[c0 + n];
            nn += tv[n] * tv[n];
        }
        nn = hred16(nn);
        const float inv = 1.f / fmaxf(sqrtf(nn), 1e-12f);

        float lg[8];
        #pragma unroll
        for (int k = 0; k < K_; ++k) {
            float p = 0.f;
            #pragma unroll
            for (int n = 0; n < 8; ++n) p = fmaf(tv[n], s_cbn[k][c0 + n], p);
            lg[k] = hred16(p) * inv;   // TEMPERATURE = 1.0
        }

        // argmax (first occurrence) + softmax, computed by every lane
        float mx = lg[0]; int idx = 0;
        #pragma unroll
        for (int k = 1; k < K_; ++k) if (lg[k] > mx) { mx = lg[k]; idx = k; }
        float e[8]; float se = 0.f;
        #pragma unroll
        for (int k = 0; k < K_; ++k) { e[k] = expf(lg[k] - mx); se += e[k]; }
        const float rse = 1.f / se;

        if (r < B) {
            // embedding = raw codebook[idx]  (straight-through == hard one-hot)
            long eb = off_emb + (long)r * D_ + c0;
            if (eb + 7 < out_size) {
                float4 v0 = *(const float4*)&s_cb[idx][c0];
                float4 v1 = *(const float4*)&s_cb[idx][c0 + 4];
                *(float4*)(out + eb)     = v0;
                *(float4*)(out + eb + 4) = v1;
            }
            if (tx == 0) {
                if (r < out_size) out[r] = (float)idx;
                long sb = off_soft + (long)r * K_;
                if (sb + 7 < out_size) {
                    #pragma unroll
                    for (int k = 0; k < K_; ++k) out[sb + k] = e[k] * rse;
                }
                long lb = off_log + (long)r * K_;
                if (lb + 7 < out_size) {
                    #pragma unroll
                    for (int k = 0; k < K_; ++k) out[lb + k] = lg[k];
                }
            }
        }
    }
}

extern "C" void kernel_launch(void* const* d_in, const int* in_sizes, int n_in,
                              void* d_out, int out_size) {
    const float* X     = (const float*)d_in[0];   // global_prosody (B,128)
    const float* W     = (const float*)d_in[1];   // (128,128)
    const float* bias  = (const float*)d_in[2];   // (128,)
    const float* gamma = (const float*)d_in[3];   // (128,)
    const float* beta  = (const float*)d_in[4];   // (128,)
    const float* cb    = (const float*)d_in[5];   // (8,128)
    float* out = (float*)d_out;

    const int B = in_sizes[0] / D_;
    const int grid = (B + 127) / 128;
    l1q_kernel<<<grid, 256>>>(X, W, bias, gamma, beta, cb, out, B, (long)out_size);
}

// round 5
// speedup vs baseline: 1.2989x; 1.2890x over previous
#include <cuda_runtime.h>
#include <cuda_fp16.h>
#include <stdint.h>
#include <math.h>

#define D_ 128
#define K_ 8
#define XS 136                 // fp16 tile stride (halves): conflict-free ldmatrix
#define YS 130                 // fp32 y tile stride (floats) — even, for aligned float2

// ---- dynamic smem layout (bytes) ----
#define SM_X1   0
#define SM_X2   34816
#define SM_W1   69632
#define SM_W2   104448
#define SM_CB   139264         // float[8][128] raw codebook
#define SM_CBN  143360         // float[8][128] normalized codebook
#define SM_BIAS 147456         // float[128]
#define SM_G    147968         // float[128]
#define SM_BT   148480         // float[128]
#define SM_NRM  148992         // float[8]
#define SMEM_TOTAL 149056

__device__ __forceinline__ uint32_t smem_u32(const void* p) {
    uint32_t a;
    asm("{ .reg .u64 t; cvta.to.shared.u64 t, %1; cvt.u32.u64 %0, t; }" : "=r"(a) : "l"(p));
    return a;
}

__device__ __forceinline__ float hred16(float v) {
    v += __shfl_xor_sync(0xffffffffu, v, 8, 16);
    v += __shfl_xor_sync(0xffffffffu, v, 4, 16);
    v += __shfl_xor_sync(0xffffffffu, v, 2, 16);
    v += __shfl_xor_sync(0xffffffffu, v, 1, 16);
    return v;
}

__device__ __forceinline__ void ldsm_x4(uint32_t& r0, uint32_t& r1, uint32_t& r2, uint32_t& r3,
                                        uint32_t addr) {
    asm volatile("ldmatrix.sync.aligned.m8n8.x4.shared.b16 {%0,%1,%2,%3}, [%4];"
                 : "=r"(r0), "=r"(r1), "=r"(r2), "=r"(r3) : "r"(addr));
}
__device__ __forceinline__ void ldsm_x2(uint32_t& r0, uint32_t& r1, uint32_t addr) {
    asm volatile("ldmatrix.sync.aligned.m8n8.x2.shared.b16 {%0,%1}, [%2];"
                 : "=r"(r0), "=r"(r1) : "r"(addr));
}
__device__ __forceinline__ void mma16816(float* c, const uint32_t* a, const uint32_t* b) {
    asm volatile(
        "mma.sync.aligned.m16n8k16.row.col.f32.f16.f16.f32 "
        "{%0,%1,%2,%3}, {%4,%5,%6,%7}, {%8,%9}, {%0,%1,%2,%3};"
        : "+f"(c[0]), "+f"(c[1]), "+f"(c[2]), "+f"(c[3])
        : "r"(a[0]), "r"(a[1]), "r"(a[2]), "r"(a[3]), "r"(b[0]), "r"(b[1]));
}

__global__ __launch_bounds__(256, 1) void l1q_mma(
    const float* __restrict__ X, const float* __restrict__ W,
    const float* __restrict__ bias, const float* __restrict__ gamma,
    const float* __restrict__ beta, const float* __restrict__ cb,
    float* __restrict__ out, int B, long out_size)
{
    extern __shared__ char smem[];
    const int tid = threadIdx.x;
    const int wid = tid >> 5;
    const int lane = tid & 31;
    const int row0 = blockIdx.x * 128;

    __half* sX1 = (__half*)(smem + SM_X1);
    __half* sX2 = (__half*)(smem + SM_X2);
    __half* sW1 = (__half*)(smem + SM_W1);
    __half* sW2 = (__half*)(smem + SM_W2);
    float* s_cb   = (float*)(smem + SM_CB);
    float* s_cbn  = (float*)(smem + SM_CBN);
    float* s_bias = (float*)(smem + SM_BIAS);
    float* s_g    = (float*)(smem + SM_G);
    float* s_bt   = (float*)(smem + SM_BT);
    float* s_nrm  = (float*)(smem + SM_NRM);
    const uint32_t sb = smem_u32(smem);

    // ---- load params + codebook ----
    for (int i = tid; i < K_ * D_; i += 256) s_cb[i] = cb[i];
    if (tid < D_) { s_bias[tid] = bias[tid]; s_g[tid] = gamma[tid]; s_bt[tid] = beta[tid]; }

    // ---- load X,W fp32 and split to fp16 hi/lo tiles ----
    {
        const int crow = tid >> 1;
        const int cc0 = (tid & 1) << 6;
        int gr = row0 + crow; if (gr >= B) gr = B - 1;
        const float* xs = X + (long)gr * D_ + cc0;
        const float* ws = W + (long)crow * D_ + cc0;
        __half* x1 = sX1 + crow * XS + cc0;
        __half* x2 = sX2 + crow * XS + cc0;
        __half* w1 = sW1 + crow * XS + cc0;
        __half* w2 = sW2 + crow * XS + cc0;
        #pragma unroll
        for (int j = 0; j < 64; j += 4) {
            float4 v = *(const float4*)(xs + j);
            __half h1[4], h2[4];
            h1[0] = __float2half_rn(v.x); h2[0] = __float2half_rn(v.x - __half2float(h1[0]));
            h1[1] = __float2half_rn(v.y); h2[1] = __float2half_rn(v.y - __half2float(h1[1]));
            h1[2] = __float2half_rn(v.z); h2[2] = __float2half_rn(v.z - __half2float(h1[2]));
            h1[3] = __float2half_rn(v.w); h2[3] = __float2half_rn(v.w - __half2float(h1[3]));
            *(uint2*)(x1 + j) = *(uint2*)h1;
            *(uint2*)(x2 + j) = *(uint2*)h2;
            float4 u = *(const float4*)(ws + j);
            h1[0] = __float2half_rn(u.x); h2[0] = __float2half_rn(u.x - __half2float(h1[0]));
            h1[1] = __float2half_rn(u.y); h2[1] = __float2half_rn(u.y - __half2float(h1[1]));
            h1[2] = __float2half_rn(u.z); h2[2] = __float2half_rn(u.z - __half2float(h1[2]));
            h1[3] = __float2half_rn(u.w); h2[3] = __float2half_rn(u.w - __half2float(h1[3]));
            *(uint2*)(w1 + j) = *(uint2*)h1;
            *(uint2*)(w2 + j) = *(uint2*)h2;
        }
    }
    __syncthreads();

    // ---- codebook normalization (cheap, before mma) ----
    if (tid < K_) {
        float s = 0.f;
        #pragma unroll 8
        for (int j = 0; j < D_; ++j) { float v = s_cb[tid * D_ + j]; s += v * v; }
        s_nrm[tid] = 1.f / fmaxf(sqrtf(s), 1e-12f);
    }
    __syncthreads();
    if (tid < D_) {
        #pragma unroll
        for (int k = 0; k < K_; ++k) s_cbn[k * D_ + tid] = s_cb[k * D_ + tid] * s_nrm[k];
    }

    // ---- mma: warp w computes rows 16w..16w+15, all 128 cols ----
    float acc[16][4];
    #pragma unroll
    for (int nt = 0; nt < 16; ++nt)
        #pragma unroll
        for (int j = 0; j < 4; ++j) acc[nt][j] = 0.f;

    const int a_row = (lane & 7) | (lane & 8);              // 0..15
    const int a_koff = (lane >> 4) << 3;                     // 0 or 8
    const int b_n  = lane & 7;                               // 0..7
    const int b_koff = ((lane >> 3) & 1) << 3;               // 0 or 8
    const uint32_t aBase1 = sb + SM_X1 + ((wid * 16 + a_row) * XS + a_koff) * 2;
    const uint32_t aBase2 = sb + SM_X2 + ((wid * 16 + a_row) * XS + a_koff) * 2;
    const uint32_t bBase1 = sb + SM_W1 + (b_n * XS + b_koff) * 2;
    const uint32_t bBase2 = sb + SM_W2 + (b_n * XS + b_koff) * 2;

    #pragma unroll
    for (int ks = 0; ks < 8; ++ks) {
        const int k0 = ks * 16;
        uint32_t A1[4], A2[4];
        ldsm_x4(A1[0], A1[1], A1[2], A1[3], aBase1 + k0 * 2);
        ldsm_x4(A2[0], A2[1], A2[2], A2[3], aBase2 + k0 * 2);
        #pragma unroll
        for (int nt = 0; nt < 16; ++nt) {
            uint32_t B1[2], B2[2];
            ldsm_x2(B1[0], B1[1], bBase1 + (nt * 8 * XS + k0) * 2);
            ldsm_x2(B2[0], B2[1], bBase2 + (nt * 8 * XS + k0) * 2);
            mma16816(acc[nt], A1, B1);   // x1*w1
            mma16816(acc[nt], A1, B2);   // x1*w2
            mma16816(acc[nt], A2, B1);   // x2*w1
        }
    }
    __syncthreads();   // all warps done reading X/W tiles

    // ---- dump accumulators to smem y tile (reuses X1/X2 space) ----
    float* ys = (float*)(smem + SM_X1);   // [128][YS]
    {
        const int g = lane >> 2, t = lane & 3;
        const int r0 = wid * 16 + g, r1 = r0 + 8;
        #pragma unroll
        for (int nt = 0; nt < 16; ++nt) {
            const int c = nt * 8 + t * 2;
            *(float2*)&ys[r0 * YS + c] = make_float2(acc[nt][0], acc[nt][1]);
            *(float2*)&ys[r1 * YS + c] = make_float2(acc[nt][2], acc[nt][3]);
        }
    }
    __syncthreads();

    // ---- round-1 epilogue: LN -> l2norm -> logits -> softmax/argmax -> outputs ----
    const long Bl = (long)B;
    const long off_soft = Bl;
    const long off_emb  = Bl + Bl * K_;
    const long off_log  = Bl + Bl * K_ + Bl * D_;
    const int tx = tid & 15;
    const int ty = tid >> 4;
    const int c0 = tx * 8;

    #pragma unroll 1
    for (int m = 0; m < 8; ++m) {
        const int lr = ty * 8 + m;
        const int r = row0 + lr;

        float hv[8];
        #pragma unroll
        for (int n = 0; n < 8; ++n) hv[n] = ys[lr * YS + c0 + n] + s_bias[c0 + n];

        float s = 0.f;
        #pragma unroll
        for (int n = 0; n < 8; ++n) s += hv[n];
        const float mu = hred16(s) * (1.f / 128.f);

        float q = 0.f;
        #pragma unroll
        for (int n = 0; n < 8; ++n) { float d = hv[n] - mu; q += d * d; }
        const float var = hred16(q) * (1.f / 128.f);
        const float rstd = rsqrtf(var + 1e-5f);

        float tv[8]; float nn = 0.f;
        #pragma unroll
        for (int n = 0; n < 8; ++n) {
            tv[n] = (hv[n] - mu) * rstd * s_g[c0 + n] + s_bt[c0 + n];
            nn += tv[n] * tv[n];
        }
        nn = hred16(nn);
        const float inv = 1.f / fmaxf(sqrtf(nn), 1e-12f);

        float lg[8];
        #pragma unroll
        for (int k = 0; k < K_; ++k) {
            float p = 0.f;
            #pragma unroll
            for (int n = 0; n < 8; ++n) p = fmaf(tv[n], s_cbn[k * D_ + c0 + n], p);
            lg[k] = hred16(p) * inv;   // TEMPERATURE = 1.0
        }

        float mx = lg[0]; int idx = 0;
        #pragma unroll
        for (int k = 1; k < K_; ++k) if (lg[k] > mx) { mx = lg[k]; idx = k; }
        float e[8]; float se = 0.f;
        #pragma unroll
        for (int k = 0; k < K_; ++k) { e[k] = expf(lg[k] - mx); se += e[k]; }
        const float rse = 1.f / se;

        if (r < B) {
            long eb = off_emb + (long)r * D_ + c0;
            if (eb + 7 < out_size) {
                float4 v0 = *(float4*)&s_cb[idx * D_ + c0];
                float4 v1 = *(float4*)&s_cb[idx * D_ + c0 + 4];
                *(float4*)(out + eb)     = v0;
                *(float4*)(out + eb + 4) = v1;
            }
            if (tx == 0) {
                if (r < out_size) out[r] = (float)idx;
                long sbo = off_soft + (long)r * K_;
                if (sbo + 7 < out_size) {
                    #pragma unroll
                    for (int k = 0; k < K_; ++k) out[sbo + k] = e[k] * rse;
                }
                long lb = off_log + (long)r * K_;
                if (lb + 7 < out_size) {
                    #pragma unroll
                    for (int k = 0; k < K_; ++k) out[lb + k] = lg[k];
                }
            }
        }
    }
}

extern "C" void kernel_launch(void* const* d_in, const int* in_sizes, int n_in,
                              void* d_out, int out_size) {
    const float* X     = (const float*)d_in[0];
    const float* W     = (const float*)d_in[1];
    const float* bias  = (const float*)d_in[2];
    const float* gamma = (const float*)d_in[3];
    const float* beta  = (const float*)d_in[4];
    const float* cb    = (const float*)d_in[5];
    float* out = (float*)d_out;

    const int B = in_sizes[0] / D_;
    const int grid = (B + 127) / 128;
    cudaFuncSetAttribute(l1q_mma, cudaFuncAttributeMaxDynamicSharedMemorySize, SMEM_TOTAL);
    l1q_mma<<<grid, 256, SMEM_TOTAL>>>(X, W, bias, gamma, beta, cb, out, B, (long)out_size);
}

// round 6
// speedup vs baseline: 1.7635x; 1.3577x over previous
#include <cuda_runtime.h>
#include <cuda_fp16.h>
#include <stdint.h>
#include <math.h>

#define D_ 128
#define K_ 8
#define XS 136                 // fp16 X tile stride (halves)
#define YS 130                 // fp32 y tile stride (floats), even

// ---- main-kernel dynamic smem layout (bytes) ----
#define SM_X1   0              // 128 x XS halves = 34816
#define SM_X2   34816
#define SM_CB   69632          // float[8][128] raw codebook
#define SM_CBN  73728          // float[8][128] normalized codebook
#define SM_BIAS 77824          // float[128]
#define SM_G    78336
#define SM_BT   78848
#define SMEM_TOTAL 79360

// W as pre-split fp16 hi/lo in m16n8k16 B-fragment order:
// g_bfrag[(ks*16 + gnt)*32 + lane] = {B1r0, B1r1, B2r0, B2r1}
__device__ uint4 g_bfrag[8 * 16 * 32];
__device__ float g_cbn[K_ * D_];

__device__ __forceinline__ uint32_t smem_u32(const void* p) {
    uint32_t a;
    asm("{ .reg .u64 t; cvta.to.shared.u64 t, %1; cvt.u32.u64 %0, t; }" : "=r"(a) : "l"(p));
    return a;
}

__device__ __forceinline__ float hred16(float v) {
    v += __shfl_xor_sync(0xffffffffu, v, 8, 16);
    v += __shfl_xor_sync(0xffffffffu, v, 4, 16);
    v += __shfl_xor_sync(0xffffffffu, v, 2, 16);
    v += __shfl_xor_sync(0xffffffffu, v, 1, 16);
    return v;
}

__device__ __forceinline__ void ldsm_x4(uint32_t& r0, uint32_t& r1, uint32_t& r2, uint32_t& r3,
                                        uint32_t addr) {
    asm volatile("ldmatrix.sync.aligned.m8n8.x4.shared.b16 {%0,%1,%2,%3}, [%4];"
                 : "=r"(r0), "=r"(r1), "=r"(r2), "=r"(r3) : "r"(addr));
}
__device__ __forceinline__ void mma16816(float* c, const uint32_t* a, uint32_t b0, uint32_t b1) {
    asm volatile(
        "mma.sync.aligned.m16n8k16.row.col.f32.f16.f16.f32 "
        "{%0,%1,%2,%3}, {%4,%5,%6,%7}, {%8,%9}, {%0,%1,%2,%3};"
        : "+f"(c[0]), "+f"(c[1]), "+f"(c[2]), "+f"(c[3])
        : "r"(a[0]), "r"(a[1]), "r"(a[2]), "r"(a[3]), "r"(b0), "r"(b1));
}

// pack two fp32 into (hi-half2, lo-half2)
__device__ __forceinline__ void split2(float x, float y, uint32_t& hi, uint32_t& lo) {
    __half hx = __float2half_rn(x), hy = __float2half_rn(y);
    __half lx = __float2half_rn(x - __half2float(hx));
    __half ly = __float2half_rn(y - __half2float(hy));
    __half2 h2 = __halves2half2(hx, hy), l2 = __halves2half2(lx, ly);
    hi = *(uint32_t*)&h2; lo = *(uint32_t*)&l2;
}

// ---- prep: W -> fragment-ordered fp16 splits; codebook -> normalized ----
__global__ void l1q_prep(const float* __restrict__ W, const float* __restrict__ cb) {
    if (blockIdx.x < 16) {
        const int t = blockIdx.x * 256 + threadIdx.x;   // 0..4095
        const int lane = t & 31;
        const int gnt = (t >> 5) & 15;
        const int ks = t >> 9;
        const int n = gnt * 8 + (lane >> 2);
        const int k0 = ks * 16 + ((lane & 3) << 1);
        const float* wr = W + n * 128;
        uint4 f;
        split2(wr[k0],     wr[k0 + 1], f.x, f.z);   // b0: k0,k0+1
        split2(wr[k0 + 8], wr[k0 + 9], f.y, f.w);   // b1: k0+8,k0+9
        g_bfrag[(ks * 16 + gnt) * 32 + lane] = f;
    } else {
        __shared__ float inv[K_];
        if (threadIdx.x < K_) {
            float s = 0.f;
            #pragma unroll 8
            for (int j = 0; j < D_; ++j) { float v = cb[threadIdx.x * D_ + j]; s += v * v; }
            inv[threadIdx.x] = 1.f / fmaxf(sqrtf(s), 1e-12f);
        }
        __syncthreads();
        for (int i = threadIdx.x; i < K_ * D_; i += 256)
            g_cbn[i] = cb[i] * inv[i >> 7];
    }
}

__global__ __launch_bounds__(256, 2) void l1q_mma(
    const float* __restrict__ X,
    const float* __restrict__ bias, const float* __restrict__ gamma,
    const float* __restrict__ beta, const float* __restrict__ cb,
    float* __restrict__ out, int B, long out_size)
{
    extern __shared__ char smem[];
    const int tid = threadIdx.x;
    const int wid = tid >> 5;
    const int lane = tid & 31;
    const int row0 = blockIdx.x * 128;

    __half* sX1 = (__half*)(smem + SM_X1);
    __half* sX2 = (__half*)(smem + SM_X2);
    float* s_cb   = (float*)(smem + SM_CB);
    float* s_cbn  = (float*)(smem + SM_CBN);
    float* s_bias = (float*)(smem + SM_BIAS);
    float* s_g    = (float*)(smem + SM_G);
    float* s_bt   = (float*)(smem + SM_BT);
    const uint32_t sb = smem_u32(smem);

    // ---- params + codebook (cbn precomputed) ----
    for (int i = tid; i < K_ * D_; i += 256) { s_cb[i] = cb[i]; s_cbn[i] = g_cbn[i]; }
    if (tid < D_) { s_bias[tid] = bias[tid]; s_g[tid] = gamma[tid]; s_bt[tid] = beta[tid]; }

    // ---- load X fp32, split to fp16 hi/lo smem tiles ----
    {
        const int crow = tid >> 1;
        const int cc0 = (tid & 1) << 6;
        int gr = row0 + crow; if (gr >= B) gr = B - 1;
        const float* xs = X + (long)gr * D_ + cc0;
        __half* x1 = sX1 + crow * XS + cc0;
        __half* x2 = sX2 + crow * XS + cc0;
        #pragma unroll
        for (int j = 0; j < 64; j += 4) {
            float4 v = *(const float4*)(xs + j);
            uint32_t h[2], l[2];
            split2(v.x, v.y, h[0], l[0]);
            split2(v.z, v.w, h[1], l[1]);
            *(uint2*)(x1 + j) = *(uint2*)h;
            *(uint2*)(x2 + j) = *(uint2*)l;
        }
    }
    __syncthreads();

    // ---- mma: warp w -> rows (w&3)*32..+31, cols (w>>2)*64..+63 ----
    const int mr = (wid & 3) * 32;
    const int ntb = (wid >> 2) * 8;             // global n-tile base

    float acc[2][8][4];
    #pragma unroll
    for (int mt = 0; mt < 2; ++mt)
        #pragma unroll
        for (int nt = 0; nt < 8; ++nt)
            #pragma unroll
            for (int j = 0; j < 4; ++j) acc[mt][nt][j] = 0.f;

    const int a_row = lane & 15;
    const int a_koff = (lane >> 4) << 3;
    const uint32_t aB1_0 = sb + SM_X1 + (uint32_t)(((mr + a_row) * XS + a_koff) * 2);
    const uint32_t aB2_0 = sb + SM_X2 + (uint32_t)(((mr + a_row) * XS + a_koff) * 2);
    const uint32_t aStep16 = 16 * XS * 2;       // +16 rows

    const uint4* __restrict__ bfrag = g_bfrag;

    #pragma unroll 2
    for (int ks = 0; ks < 8; ++ks) {
        const int k0 = ks * 16;
        uint32_t A1[2][4], A2[2][4];
        ldsm_x4(A1[0][0], A1[0][1], A1[0][2], A1[0][3], aB1_0 + k0 * 2);
        ldsm_x4(A1[1][0], A1[1][1], A1[1][2], A1[1][3], aB1_0 + aStep16 + k0 * 2);
        ldsm_x4(A2[0][0], A2[0][1], A2[0][2], A2[0][3], aB2_0 + k0 * 2);
        ldsm_x4(A2[1][0], A2[1][1], A2[1][2], A2[1][3], aB2_0 + aStep16 + k0 * 2);
        #pragma unroll
        for (int nt = 0; nt < 8; ++nt) {
            uint4 f = __ldg(&bfrag[(ks * 16 + ntb + nt) * 32 + lane]);
            #pragma unroll
            for (int mt = 0; mt < 2; ++mt) {
                mma16816(acc[mt][nt], A1[mt], f.x, f.y);   // x1*w1
                mma16816(acc[mt][nt], A1[mt], f.z, f.w);   // x1*w2
                mma16816(acc[mt][nt], A2[mt], f.x, f.y);   // x2*w1
            }
        }
    }
    __syncthreads();   // all warps done reading X tiles

    // ---- dump accumulators to smem y tile (reuses X1/X2 space) ----
    float* ys = (float*)(smem + SM_X1);   // [128][YS]
    {
        const int g = lane >> 2, t4 = lane & 3;
        #pragma unroll
        for (int mt = 0; mt < 2; ++mt) {
            const int r0 = mr + mt * 16 + g, r1 = r0 + 8;
            #pragma unroll
            for (int nt = 0; nt < 8; ++nt) {
                const int c = ntb * 8 + nt * 8 + t4 * 2;
                *(float2*)&ys[r0 * YS + c] = make_float2(acc[mt][nt][0], acc[mt][nt][1]);
                *(float2*)&ys[r1 * YS + c] = make_float2(acc[mt][nt][2], acc[mt][nt][3]);
            }
        }
    }
    __syncthreads();

    // ---- epilogue: LN -> l2norm -> logits -> softmax/argmax -> outputs ----
    const long Bl = (long)B;
    const long off_soft = Bl;
    const long off_emb  = Bl + Bl * K_;
    const long off_log  = Bl + Bl * K_ + Bl * D_;
    const int tx = tid & 15;
    const int ty = tid >> 4;
    const int c0 = tx * 8;

    #pragma unroll 1
    for (int m = 0; m < 8; ++m) {
        const int lr = ty * 8 + m;
        const int r = row0 + lr;

        float hv[8];
        #pragma unroll
        for (int n = 0; n < 8; ++n) hv[n] = ys[lr * YS + c0 + n] + s_bias[c0 + n];

        float s = 0.f;
        #pragma unroll
        for (int n = 0; n < 8; ++n) s += hv[n];
        const float mu = hred16(s) * (1.f / 128.f);

        float q = 0.f;
        #pragma unroll
        for (int n = 0; n < 8; ++n) { float d = hv[n] - mu; q += d * d; }
        const float var = hred16(q) * (1.f / 128.f);
        const float rstd = rsqrtf(var + 1e-5f);

        float tv[8]; float nn = 0.f;
        #pragma unroll
        for (int n = 0; n < 8; ++n) {
            tv[n] = (hv[n] - mu) * rstd * s_g[c0 + n] + s_bt[c0 + n];
            nn += tv[n] * tv[n];
        }
        nn = hred16(nn);
        const float inv = 1.f / fmaxf(sqrtf(nn), 1e-12f);

        float lg[8];
        #pragma unroll
        for (int k = 0; k < K_; ++k) {
            float p = 0.f;
            #pragma unroll
            for (int n = 0; n < 8; ++n) p = fmaf(tv[n], s_cbn[k * D_ + c0 + n], p);
            lg[k] = hred16(p) * inv;   // TEMPERATURE = 1.0
        }

        float mx = lg[0]; int idx = 0;
        #pragma unroll
        for (int k = 1; k < K_; ++k) if (lg[k] > mx) { mx = lg[k]; idx = k; }
        float e[8]; float se = 0.f;
        #pragma unroll
        for (int k = 0; k < K_; ++k) { e[k] = expf(lg[k] - mx); se += e[k]; }
        const float rse = 1.f / se;

        if (r < B) {
            long eb = off_emb + (long)r * D_ + c0;
            if (eb + 7 < out_size) {
                float4 v0 = *(float4*)&s_cb[idx * D_ + c0];
                float4 v1 = *(float4*)&s_cb[idx * D_ + c0 + 4];
                *(float4*)(out + eb)     = v0;
                *(float4*)(out + eb + 4) = v1;
            }
            if (tx == 0) {
                if (r < out_size) out[r] = (float)idx;
                long sbo = off_soft + (long)r * K_;
                if (sbo + 7 < out_size) {
                    #pragma unroll
                    for (int k = 0; k < K_; ++k) out[sbo + k] = e[k] * rse;
                }
                long lb = off_log + (long)r * K_;
                if (lb + 7 < out_size) {
                    #pragma unroll
                    for (int k = 0; k < K_; ++k) out[lb + k] = lg[k];
                }
            }
        }
    }
}

extern "C" void kernel_launch(void* const* d_in, const int* in_sizes, int n_in,
                              void* d_out, int out_size) {
    const float* X     = (const float*)d_in[0];
    const float* W     = (const float*)d_in[1];
    const float* bias  = (const float*)d_in[2];
    const float* gamma = (const float*)d_in[3];
    const float* beta  = (const float*)d_in[4];
    const float* cb    = (const float*)d_in[5];
    float* out = (float*)d_out;

    const int B = in_sizes[0] / D_;
    const int grid = (B + 127) / 128;
    l1q_prep<<<17, 256>>>(W, cb);
    cudaFuncSetAttribute(l1q_mma, cudaFuncAttributeMaxDynamicSharedMemorySize, SMEM_TOTAL);
    l1q_mma<<<grid, 256, SMEM_TOTAL>>>(X, bias, gamma, beta, cb, out, B, (long)out_size);
}

// round 7
// speedup vs baseline: 2.9235x; 1.6578x over previous
#include <cuda_runtime.h>
#include <cuda_fp16.h>
#include <stdint.h>
#include <math.h>

#define D_ 128
#define K_ 8
#define XS 136                 // fp16 X tile stride (halves)

// ---- main-kernel dynamic smem layout (bytes) ----
#define SM_X1    0             // 128 x XS halves = 34816
#define SM_X2    34816
#define SM_CB    69632         // float[8][128] raw codebook (embedding gather)
#define SM_PACK  73728         // float4[128*3] per-column consts
#define SM_IDX   79872         // int[128]
#define SMEM_TOTAL 80384

// W pre-split fp16 hi/lo in m16n8k16 B-fragment order:
// g_bfrag[(ks*16 + gnt)*32 + lane] = {B1r0, B1r1, B2r0, B2r1}
__device__ uint4 g_bfrag[8 * 16 * 32];
// per-column packed consts: [c*3+0]={bias, g*g, g*bt, 0}, [c*3+1]={g*cbn[0..3]}, [c*3+2]={g*cbn[4..7]}
__device__ float4 g_packc[128 * 3];
// scalars: [0]=Sum g^2, [1]=Sum g*bt, [2]=Sum bt^2, [3+k]=e[k]=Sum g*cbn[k], [11+k]=d[k]=Sum bt*cbn[k]
__device__ float g_sc[19];

__device__ __forceinline__ uint32_t smem_u32(const void* p) {
    uint32_t a;
    asm("{ .reg .u64 t; cvta.to.shared.u64 t, %1; cvt.u32.u64 %0, t; }" : "=r"(a) : "l"(p));
    return a;
}
__device__ __forceinline__ void ldsm_x4(uint32_t& r0, uint32_t& r1, uint32_t& r2, uint32_t& r3,
                                        uint32_t addr) {
    asm volatile("ldmatrix.sync.aligned.m8n8.x4.shared.b16 {%0,%1,%2,%3}, [%4];"
                 : "=r"(r0), "=r"(r1), "=r"(r2), "=r"(r3) : "r"(addr));
}
__device__ __forceinline__ void mma16816(float* c, const uint32_t* a, uint32_t b0, uint32_t b1) {
    asm volatile(
        "mma.sync.aligned.m16n8k16.row.col.f32.f16.f16.f32 "
        "{%0,%1,%2,%3}, {%4,%5,%6,%7}, {%8,%9}, {%0,%1,%2,%3};"
        : "+f"(c[0]), "+f"(c[1]), "+f"(c[2]), "+f"(c[3])
        : "r"(a[0]), "r"(a[1]), "r"(a[2]), "r"(a[3]), "r"(b0), "r"(b1));
}
__device__ __forceinline__ void split2(float x, float y, uint32_t& hi, uint32_t& lo) {
    __half hx = __float2half_rn(x), hy = __float2half_rn(y);
    __half lx = __float2half_rn(x - __half2float(hx));
    __half ly = __float2half_rn(y - __half2float(hy));
    __half2 h2 = __halves2half2(hx, hy), l2 = __halves2half2(lx, ly);
    hi = *(uint32_t*)&h2; lo = *(uint32_t*)&l2;
}
__device__ __forceinline__ float red4(float v) {
    v += __shfl_xor_sync(0xffffffffu, v, 1);
    v += __shfl_xor_sync(0xffffffffu, v, 2);
    return v;
}

// ---- prep: W -> fragment-order fp16 splits; codebook -> packed consts ----
__global__ void l1q_prep(const float* __restrict__ W, const float* __restrict__ cb,
                         const float* __restrict__ bias, const float* __restrict__ gamma,
                         const float* __restrict__ beta) {
    if (blockIdx.x < 16) {
        const int t = blockIdx.x * 256 + threadIdx.x;   // 0..4095
        const int lane = t & 31;
        const int gnt = (t >> 5) & 15;
        const int ks = t >> 9;
        const int n = gnt * 8 + (lane >> 2);
        const int k0 = ks * 16 + ((lane & 3) << 1);
        const float* wr = W + n * 128;
        uint4 f;
        split2(wr[k0],     wr[k0 + 1], f.x, f.z);
        split2(wr[k0 + 8], wr[k0 + 9], f.y, f.w);
        g_bfrag[(ks * 16 + gnt) * 32 + lane] = f;
    } else {
        __shared__ float inv[K_];
        __shared__ float cbn[K_ * D_];
        __shared__ float red[19][128];
        const int tid = threadIdx.x;
        if (tid < K_) {
            float s = 0.f;
            #pragma unroll 8
            for (int j = 0; j < D_; ++j) { float v = cb[tid * D_ + j]; s += v * v; }
            inv[tid] = 1.f / fmaxf(sqrtf(s), 1e-12f);
        }
        __syncthreads();
        for (int i = tid; i < K_ * D_; i += 256) cbn[i] = cb[i] * inv[i >> 7];
        __syncthreads();
        if (tid < D_) {
            const int c = tid;
            float g = gamma[c], bt = beta[c], bs = bias[c];
            float4 pa = make_float4(bs, g * g, g * bt, 0.f);
            float4 pb, pc;
            pb.x = g * cbn[0 * D_ + c]; pb.y = g * cbn[1 * D_ + c];
            pb.z = g * cbn[2 * D_ + c]; pb.w = g * cbn[3 * D_ + c];
            pc.x = g * cbn[4 * D_ + c]; pc.y = g * cbn[5 * D_ + c];
            pc.z = g * cbn[6 * D_ + c]; pc.w = g * cbn[7 * D_ + c];
            g_packc[c * 3 + 0] = pa;
            g_packc[c * 3 + 1] = pb;
            g_packc[c * 3 + 2] = pc;
            red[0][c] = g * g;
            red[1][c] = g * bt;
            red[2][c] = bt * bt;
            #pragma unroll
            for (int k = 0; k < K_; ++k) {
                red[3 + k][c]  = g * cbn[k * D_ + c];
                red[11 + k][c] = bt * cbn[k * D_ + c];
            }
        }
        __syncthreads();
        if (tid < 19) {
            float s = 0.f;
            for (int c = 0; c < D_; ++c) s += red[tid][c];
            g_sc[tid] = s;
        }
    }
}

__global__ __launch_bounds__(256, 2) void l1q_mma(
    const float* __restrict__ X, const float* __restrict__ cb,
    float* __restrict__ out, int B, long out_size)
{
    extern __shared__ char smem[];
    const int tid = threadIdx.x;
    const int wid = tid >> 5;
    const int lane = tid & 31;
    const int row0 = blockIdx.x * 128;

    __half* sX1 = (__half*)(smem + SM_X1);
    __half* sX2 = (__half*)(smem + SM_X2);
    float*  s_cb = (float*)(smem + SM_CB);
    float4* s_pk = (float4*)(smem + SM_PACK);
    int*    s_idx = (int*)(smem + SM_IDX);
    const uint32_t sb = smem_u32(smem);

    // ---- stage codebook + packed consts ----
    for (int i = tid; i < K_ * D_; i += 256) s_cb[i] = cb[i];
    for (int i = tid; i < 128 * 3; i += 256) s_pk[i] = g_packc[i];

    // ---- load X fp32, split to fp16 hi/lo smem tiles ----
    {
        const int crow = tid >> 1;
        const int cc0 = (tid & 1) << 6;
        int gr = row0 + crow; if (gr >= B) gr = B - 1;
        const float* xs = X + (long)gr * D_ + cc0;
        __half* x1 = sX1 + crow * XS + cc0;
        __half* x2 = sX2 + crow * XS + cc0;
        #pragma unroll
        for (int j = 0; j < 64; j += 4) {
            float4 v = *(const float4*)(xs + j);
            uint32_t h[2], l[2];
            split2(v.x, v.y, h[0], l[0]);
            split2(v.z, v.w, h[1], l[1]);
            *(uint2*)(x1 + j) = *(uint2*)h;
            *(uint2*)(x2 + j) = *(uint2*)l;
        }
    }
    __syncthreads();

    // ---- mma: warp w -> rows 16w..16w+15, all 128 cols ----
    float acc[16][4];
    #pragma unroll
    for (int nt = 0; nt < 16; ++nt)
        #pragma unroll
        for (int j = 0; j < 4; ++j) acc[nt][j] = 0.f;

    const int a_row = lane & 15;
    const int a_koff = (lane >> 4) << 3;
    const uint32_t aB1 = sb + SM_X1 + (uint32_t)(((wid * 16 + a_row) * XS + a_koff) * 2);
    const uint32_t aB2 = sb + SM_X2 + (uint32_t)(((wid * 16 + a_row) * XS + a_koff) * 2);
    const uint4* __restrict__ bfrag = g_bfrag;

    #pragma unroll 2
    for (int ks = 0; ks < 8; ++ks) {
        const int k0 = ks * 16;
        uint32_t A1[4], A2[4];
        ldsm_x4(A1[0], A1[1], A1[2], A1[3], aB1 + k0 * 2);
        ldsm_x4(A2[0], A2[1], A2[2], A2[3], aB2 + k0 * 2);
        #pragma unroll
        for (int nt = 0; nt < 16; ++nt) {
            uint4 f = __ldg(&bfrag[(ks * 16 + nt) * 32 + lane]);
            mma16816(acc[nt], A1, f.x, f.y);   // x1*w1
            mma16816(acc[nt], A1, f.z, f.w);   // x1*w2
            mma16816(acc[nt], A2, f.x, f.y);   // x2*w1
        }
    }

    // ---- fragment-domain epilogue: 13 weighted sums per row ----
    // rowhalf 0: row = 16*wid + (lane>>2); rowhalf 1: +8. cols = nt*8 + (lane&3)*2 + {0,1}
    const int g4 = lane >> 2, t4 = lane & 3;
    float s1[2] = {0,0}, s2[2] = {0,0}, s3[2] = {0,0}, s4[2] = {0,0}, s5[2] = {0,0};
    float S[2][8];
    #pragma unroll
    for (int rh = 0; rh < 2; ++rh)
        #pragma unroll
        for (int k = 0; k < 8; ++k) S[rh][k] = 0.f;

    #pragma unroll
    for (int nt = 0; nt < 16; ++nt) {
        const int cA = nt * 8 + t4 * 2;
        float4 pA0 = s_pk[cA * 3], pA1 = s_pk[cA * 3 + 1], pA2 = s_pk[cA * 3 + 2];
        float4 pB0 = s_pk[cA * 3 + 3], pB1 = s_pk[cA * 3 + 4], pB2 = s_pk[cA * 3 + 5];
        #pragma unroll
        for (int rh = 0; rh < 2; ++rh) {
            {   // col cA
                float h = acc[nt][rh * 2] + pA0.x;
                float hg2 = h * pA0.y;
                s1[rh] += h;
                s2[rh] = fmaf(h, h, s2[rh]);
                s3[rh] = fmaf(hg2, h, s3[rh]);
                s4[rh] += hg2;
                s5[rh] = fmaf(h, pA0.z, s5[rh]);
                S[rh][0] = fmaf(h, pA1.x, S[rh][0]); S[rh][1] = fmaf(h, pA1.y, S[rh][1]);
                S[rh][2] = fmaf(h, pA1.z, S[rh][2]); S[rh][3] = fmaf(h, pA1.w, S[rh][3]);
                S[rh][4] = fmaf(h, pA2.x, S[rh][4]); S[rh][5] = fmaf(h, pA2.y, S[rh][5]);
                S[rh][6] = fmaf(h, pA2.z, S[rh][6]); S[rh][7] = fmaf(h, pA2.w, S[rh][7]);
            }
            {   // col cA+1
                float h = acc[nt][rh * 2 + 1] + pB0.x;
                float hg2 = h * pB0.y;
                s1[rh] += h;
                s2[rh] = fmaf(h, h, s2[rh]);
                s3[rh] = fmaf(hg2, h, s3[rh]);
                s4[rh] += hg2;
                s5[rh] = fmaf(h, pB0.z, s5[rh]);
                S[rh][0] = fmaf(h, pB1.x, S[rh][0]); S[rh][1] = fmaf(h, pB1.y, S[rh][1]);
                S[rh][2] = fmaf(h, pB1.z, S[rh][2]); S[rh][3] = fmaf(h, pB1.w, S[rh][3]);
                S[rh][4] = fmaf(h, pB2.x, S[rh][4]); S[rh][5] = fmaf(h, pB2.y, S[rh][5]);
                S[rh][6] = fmaf(h, pB2.z, S[rh][6]); S[rh][7] = fmaf(h, pB2.w, S[rh][7]);
            }
        }
    }

    // reduce over the 4 lanes owning each row
    #pragma unroll
    for (int rh = 0; rh < 2; ++rh) {
        s1[rh] = red4(s1[rh]); s2[rh] = red4(s2[rh]); s3[rh] = red4(s3[rh]);
        s4[rh] = red4(s4[rh]); s5[rh] = red4(s5[rh]);
        #pragma unroll
        for (int k = 0; k < 8; ++k) S[rh][k] = red4(S[rh][k]);
    }

    const long Bl = (long)B;
    const long off_soft = Bl;
    const long off_emb  = Bl + Bl * K_;
    const long off_log  = Bl + Bl * K_ + Bl * D_;

    if (t4 == 0) {
        const float Sg2  = __ldg(g_sc + 0);
        const float Sgbt = __ldg(g_sc + 1);
        const float Sbt2 = __ldg(g_sc + 2);
        float ek[8], dk[8];
        #pragma unroll
        for (int k = 0; k < 8; ++k) { ek[k] = __ldg(g_sc + 3 + k); dk[k] = __ldg(g_sc + 11 + k); }

        #pragma unroll
        for (int rh = 0; rh < 2; ++rh) {
            const int row = wid * 16 + rh * 8 + g4;
            const int r = row0 + row;
            const float mu = s1[rh] * (1.f / 128.f);
            const float var = s2[rh] * (1.f / 128.f) - mu * mu;
            const float rstd = rsqrtf(var + 1e-5f);
            const float nn = rstd * rstd * (s3[rh] - 2.f * mu * s4[rh] + mu * mu * Sg2)
                           + 2.f * rstd * (s5[rh] - mu * Sgbt) + Sbt2;
            const float rinv = 1.f / fmaxf(sqrtf(nn), 1e-12f);

            float lg[8];
            #pragma unroll
            for (int k = 0; k < 8; ++k)
                lg[k] = (rstd * (S[rh][k] - mu * ek[k]) + dk[k]) * rinv;

            float mx = lg[0]; int idx = 0;
            #pragma unroll
            for (int k = 1; k < 8; ++k) if (lg[k] > mx) { mx = lg[k]; idx = k; }
            float e[8]; float se = 0.f;
            #pragma unroll
            for (int k = 0; k < 8; ++k) { e[k] = expf(lg[k] - mx); se += e[k]; }
            const float rse = 1.f / se;

            s_idx[row] = idx;
            if (r < B) {
                if (r < out_size) out[r] = (float)idx;
                long sbo = off_soft + (long)r * K_;
                if (sbo + 7 < out_size) {
                    *(float4*)(out + sbo)     = make_float4(e[0]*rse, e[1]*rse, e[2]*rse, e[3]*rse);
                    *(float4*)(out + sbo + 4) = make_float4(e[4]*rse, e[5]*rse, e[6]*rse, e[7]*rse);
                }
                long lb = off_log + (long)r * K_;
                if (lb + 7 < out_size) {
                    *(float4*)(out + lb)     = make_float4(lg[0], lg[1], lg[2], lg[3]);
                    *(float4*)(out + lb + 4) = make_float4(lg[4], lg[5], lg[6], lg[7]);
                }
            }
        }
    }
    __syncthreads();

    // ---- embedding: coalesced gather of codebook[idx] ----
    for (int i = tid; i < 128 * 32; i += 256) {
        int row = i >> 5, c4 = i & 31;
        int r = row0 + row;
        if (r < B) {
            long eb = off_emb + (long)r * D_ + c4 * 4;
            if (eb + 3 < out_size) {
                float4 v = ((float4*)(s_cb + s_idx[row] * D_))[c4];
                *(float4*)(out + eb) = v;
            }
        }
    }
}

extern "C" void kernel_launch(void* const* d_in, const int* in_sizes, int n_in,
                              void* d_out, int out_size) {
    const float* X     = (const float*)d_in[0];
    const float* W     = (const float*)d_in[1];
    const float* bias  = (const float*)d_in[2];
    const float* gamma = (const float*)d_in[3];
    const float* beta  = (const float*)d_in[4];
    const float* cb    = (const float*)d_in[5];
    float* out = (float*)d_out;

    const int B = in_sizes[0] / D_;
    const int grid = (B + 127) / 128;
    l1q_prep<<<17, 256>>>(W, cb, bias, gamma, beta);
    cudaFuncSetAttribute(l1q_mma, cudaFuncAttributeMaxDynamicSharedMemorySize, SMEM_TOTAL);
    l1q_mma<<<grid, 256, SMEM_TOTAL>>>(X, cb, out, B, (long)out_size);
}